// round 6
// baseline (speedup 1.0000x reference)
#include <cuda_runtime.h>
#include <cstdint>
#include <cstddef>

#define LATENT   2000
#define NG       10000
#define KER      20
#define BATCH    128
#define NTILE    80          // groups per CTA; 10000 = 125*80
#define NCTA     125
#define NTIL     125         // K16 tiles: 2000 = 125*16 exactly
#define PITCH    80          // bytes per staged row (16 bf16 = 32B data + pad) conflict-free
#define SROWS    208         // 128 A rows + 80 B rows
#define STG_BYTES (SROWS*PITCH)          // 16640

#define OFF_STG  0                        // 2 stages
#define OFF_HS   (2*STG_BYTES)            // 33280 : h_s 128*80 f32
#define OFF_RS   (OFF_HS + 40960)         // 74240 : red_s 4*80
#define OFF_RQ   (OFF_RS + 1280)          // 75520 : red_q 4*80
#define OFF_SSC  (OFF_RQ + 1280)          // 76800
#define OFF_SSH  (OFF_SSC + 320)          // 77120
#define OFF_SCW  (OFF_SSH + 320)          // 77440 : conv_w 80*20
#define OFF_SCB  (OFF_SCW + 6400)         // 83840
#define SMEM_BYTES (OFF_SCB + 320)        // 84160

__device__ __forceinline__ uint32_t packbf(float lo, float hi) {
    uint32_t r;
    asm("cvt.rn.bf16x2.f32 %0, %1, %2;" : "=r"(r) : "f"(hi), "f"(lo));
    return r;
}
__device__ __forceinline__ void ldsm4(uint32_t* r, uint32_t a) {
    asm volatile("ldmatrix.sync.aligned.m8n8.x4.shared.b16 {%0,%1,%2,%3}, [%4];"
        : "=r"(r[0]), "=r"(r[1]), "=r"(r[2]), "=r"(r[3]) : "r"(a));
}
__device__ __forceinline__ void ldsm2(uint32_t* r, uint32_t a) {
    asm volatile("ldmatrix.sync.aligned.m8n8.x2.shared.b16 {%0,%1}, [%2];"
        : "=r"(r[0]), "=r"(r[1]) : "r"(a));
}
__device__ __forceinline__ void mma16816(float* d, const uint32_t* a, uint32_t b0, uint32_t b1) {
    asm volatile(
        "mma.sync.aligned.m16n8k16.row.col.f32.bf16.bf16.f32 "
        "{%0,%1,%2,%3}, {%4,%5,%6,%7}, {%8,%9}, {%0,%1,%2,%3};\n"
        : "+f"(d[0]), "+f"(d[1]), "+f"(d[2]), "+f"(d[3])
        : "r"(a[0]), "r"(a[1]), "r"(a[2]), "r"(a[3]), "r"(b0), "r"(b1));
}
__device__ __forceinline__ float sigf(float y) {
    return __fdividef(1.f, 1.f + __expf(-y));
}

__global__ void __launch_bounds__(512, 1)
fused_decoder(const float* __restrict__ z,
              const float* __restrict__ Wfc,
              const float* __restrict__ gamma,
              const float* __restrict__ beta,
              const float* __restrict__ convw,
              const float* __restrict__ convb,
              float* __restrict__ out)
{
    extern __shared__ char smem[];
    float* h_s    = (float*)(smem + OFF_HS);
    float* red_s  = (float*)(smem + OFF_RS);
    float* red_q  = (float*)(smem + OFF_RQ);
    float* sscale = (float*)(smem + OFF_SSC);
    float* sshift = (float*)(smem + OFF_SSH);
    float* scw    = (float*)(smem + OFF_SCW);
    float* scb    = (float*)(smem + OFF_SCB);

    const int tid  = threadIdx.x;
    const int w    = tid >> 5;
    const int lane = tid & 31;
    const int kq   = lane & 3;
    const int rq   = lane >> 2;
    const int g0   = blockIdx.x * NTILE;

    uint32_t smem_u32;
    asm("{ .reg .u64 t; cvta.to.shared.u64 t, %1; cvt.u32.u64 %0, t; }"
        : "=r"(smem_u32) : "l"(smem));
    const uint32_t stg_u32 = smem_u32 + OFF_STG;

    // conv params (overlaps with producer prologue LDGs)
    for (int i = tid; i < NTILE * KER; i += 512)
        scw[i] = convw[(size_t)g0 * KER + i];
    if (tid < NTILE) scb[tid] = convb[g0 + tid];

    // ---------- MMA-warp ldmatrix lane offsets (warps 0..7: m32 x n40) ----------
    const int mb = (w & 3) * 32;          // m block
    const int nh = (w >> 2) * 40;         // n half
    const uint32_t r16  = lane & 15;
    const uint32_t kh16 = (lane >> 4) * 16;
    const uint32_t aoff0 = (uint32_t)(mb + r16) * PITCH + kh16;          // A mt=0
    const uint32_t aoff1 = aoff0 + 16 * PITCH;                           // A mt=1
    const uint32_t brow  = 128 + nh + ((lane >> 4) << 3) + (lane & 7);
    const uint32_t bcol  = ((lane >> 3) & 1) * 16;
    const uint32_t boff0 = brow * PITCH + bcol;                          // B nt{0,1}
    const uint32_t boff1 = boff0 + 16 * PITCH;                           // B nt{2,3}
    const uint32_t boff2 = (uint32_t)(128 + nh + 32 + (lane & 7)) * PITCH + bcol; // B nt4 (x2)

    // ---------- producer setup (warps 8..15; 256 threads; 832 chunks) ----------
    const int p = (tid >= 256) ? tid - 256 : 0;
    const int nch = (p < 64) ? 4 : 3;     // chunks per producer thread
    const float* srcp[4];
    int stoff[4];
    #pragma unroll
    for (int j = 0; j < 4; ++j) {
        const int c = p + j * 256;
        const int cc = (c < 832) ? c : 0;
        const int row  = cc >> 2;
        const int col4 = cc & 3;
        srcp[j]  = (row < 128) ? z + (size_t)row * LATENT + col4 * 4
                               : Wfc + (size_t)(g0 + row - 128) * LATENT + col4 * 4;
        stoff[j] = row * PITCH + col4 * 8;
    }
    float4 fifo[4][4];   // 4-tile-deep register FIFO
    auto ldg_tile = [&](int t, int slot) {
        #pragma unroll
        for (int j = 0; j < 4; ++j) {
            if (j >= nch) break;
            fifo[slot][j] = *(const float4*)(srcp[j] + t * 16);
        }
    };
    auto cvt_sts = [&](int slot, int stage) {
        char* base = smem + OFF_STG + stage * STG_BYTES;
        #pragma unroll
        for (int j = 0; j < 4; ++j) {
            if (j >= nch) break;
            const float4 f = fifo[slot][j];
            uint2 u;
            u.x = packbf(f.x, f.y);
            u.y = packbf(f.z, f.w);
            *(uint2*)(base + stoff[j]) = u;
        }
    };

    float d[2][5][4];
    #pragma unroll
    for (int a = 0; a < 2; ++a)
        #pragma unroll
        for (int b = 0; b < 5; ++b)
            #pragma unroll
            for (int c = 0; c < 4; ++c) d[a][b][c] = 0.f;

    // ---------- prologue: producers fill FIFO 4 deep, stage tile 0 ----------
    if (w >= 8) {
        ldg_tile(0, 0); ldg_tile(1, 1); ldg_tile(2, 2); ldg_tile(3, 3);
        cvt_sts(0, 0);
    }
    __syncthreads();

    // ---------- main loop: 125 tiles, unroll 4 (static FIFO/stage indices) ----------
    #pragma unroll 1
    for (int tb = 0; tb < 32; ++tb) {
        #pragma unroll
        for (int i = 0; i < 4; ++i) {
            const int t = tb * 4 + i;
            if (t < NTIL) {
                if (w < 8) {
                    const uint32_t base = stg_u32 + (uint32_t)(i & 1) * STG_BYTES;
                    uint32_t A0[4], A1[4], B0[4], B1[4], B2[2];
                    ldsm4(A0, base + aoff0);
                    ldsm4(A1, base + aoff1);
                    ldsm4(B0, base + boff0);
                    ldsm4(B1, base + boff1);
                    ldsm2(B2, base + boff2);
                    mma16816(d[0][0], A0, B0[0], B0[1]);
                    mma16816(d[0][1], A0, B0[2], B0[3]);
                    mma16816(d[0][2], A0, B1[0], B1[1]);
                    mma16816(d[0][3], A0, B1[2], B1[3]);
                    mma16816(d[0][4], A0, B2[0], B2[1]);
                    mma16816(d[1][0], A1, B0[0], B0[1]);
                    mma16816(d[1][1], A1, B0[2], B0[3]);
                    mma16816(d[1][2], A1, B1[0], B1[1]);
                    mma16816(d[1][3], A1, B1[2], B1[3]);
                    mma16816(d[1][4], A1, B2[0], B2[1]);
                } else {
                    if (t + 1 < NTIL) cvt_sts((i + 1) & 3, (i + 1) & 1);
                    if (t + 4 < NTIL) ldg_tile(t + 4, i);
                }
                __syncthreads();
            }
        }
    }

    // ---------- BatchNorm stats (b_fc cancels under mean subtraction) ----------
    if (w < 8) {
        #pragma unroll
        for (int nt = 0; nt < 5; ++nt) {
            float s0 = d[0][nt][0] + d[0][nt][2] + d[1][nt][0] + d[1][nt][2];
            float s1 = d[0][nt][1] + d[0][nt][3] + d[1][nt][1] + d[1][nt][3];
            float q0 = d[0][nt][0]*d[0][nt][0] + d[0][nt][2]*d[0][nt][2]
                     + d[1][nt][0]*d[1][nt][0] + d[1][nt][2]*d[1][nt][2];
            float q1 = d[0][nt][1]*d[0][nt][1] + d[0][nt][3]*d[0][nt][3]
                     + d[1][nt][1]*d[1][nt][1] + d[1][nt][3]*d[1][nt][3];
            #pragma unroll
            for (int o = 4; o < 32; o <<= 1) {
                s0 += __shfl_xor_sync(0xffffffffu, s0, o);
                s1 += __shfl_xor_sync(0xffffffffu, s1, o);
                q0 += __shfl_xor_sync(0xffffffffu, q0, o);
                q1 += __shfl_xor_sync(0xffffffffu, q1, o);
            }
            if (rq == 0) {
                const int n = nh + nt * 8 + kq * 2;
                red_s[(w & 3) * 80 + n]     = s0;
                red_s[(w & 3) * 80 + n + 1] = s1;
                red_q[(w & 3) * 80 + n]     = q0;
                red_q[(w & 3) * 80 + n + 1] = q1;
            }
        }
    }
    __syncthreads();
    if (tid < NTILE) {
        float s = 0.f, q = 0.f;
        #pragma unroll
        for (int i = 0; i < 4; ++i) { s += red_s[i * 80 + tid]; q += red_q[i * 80 + tid]; }
        const float mean = s * (1.f / BATCH);
        const float var  = q * (1.f / BATCH) - mean * mean;
        const float scv  = gamma[g0 + tid] * rsqrtf(var + 1e-5f);
        sscale[tid] = scv;
        sshift[tid] = beta[g0 + tid] - mean * scv;
    }
    __syncthreads();

    // ---------- normalize + LeakyReLU -> h_s ----------
    if (w < 8) {
        #pragma unroll
        for (int mt = 0; mt < 2; ++mt)
            #pragma unroll
            for (int nt = 0; nt < 5; ++nt)
                #pragma unroll
                for (int c = 0; c < 4; ++c) {
                    const int n = nh + nt * 8 + kq * 2 + (c & 1);
                    const int m = mb + mt * 16 + rq + ((c >> 1) << 3);
                    float hn = d[mt][nt][c] * sscale[n] + sshift[n];
                    hn = fmaxf(hn, 0.1f * hn);
                    h_s[m * 80 + n] = hn;
                }
    }
    __syncthreads();

    // ---------- epilogue: conv outer product + LeakyReLU + sigmoid, coalesced ----------
    const size_t outb = (size_t)g0 * KER;
    for (int i = tid; i < 128 * 400; i += 512) {
        const int m = i / 400;
        const int j = (i - m * 400) * 4;     // 20 % 4 == 0
        const int n = j / 20;
        const int k = j - n * 20;
        const float hn = h_s[m * 80 + n];
        const float cb = scb[n];
        const float4 wv = *(const float4*)&scw[n * KER + k];
        float4 y;
        float t0 = hn * wv.x + cb; t0 = fmaxf(t0, 0.1f * t0); y.x = sigf(t0);
        float t1 = hn * wv.y + cb; t1 = fmaxf(t1, 0.1f * t1); y.y = sigf(t1);
        float t2 = hn * wv.z + cb; t2 = fmaxf(t2, 0.1f * t2); y.z = sigf(t2);
        float t3 = hn * wv.w + cb; t3 = fmaxf(t3, 0.1f * t3); y.w = sigf(t3);
        *(float4*)(out + (size_t)m * ((size_t)NG * KER) + outb + j) = y;
    }
}

extern "C" void kernel_launch(void* const* d_in, const int* in_sizes, int n_in,
                              void* d_out, int out_size) {
    const float* z     = (const float*)d_in[0];
    const float* Wfc   = (const float*)d_in[1];
    // d_in[2] = b_fc: cancelled analytically by BN mean subtraction
    const float* gamma = (const float*)d_in[3];
    const float* beta  = (const float*)d_in[4];
    const float* convw = (const float*)d_in[5];
    const float* convb = (const float*)d_in[6];
    cudaFuncSetAttribute(fused_decoder, cudaFuncAttributeMaxDynamicSharedMemorySize, SMEM_BYTES);
    fused_decoder<<<NCTA, 512, SMEM_BYTES>>>(z, Wfc, gamma, beta, convw, convb, (float*)d_out);
}

// round 7
// speedup vs baseline: 1.0820x; 1.0820x over previous
#include <cuda_runtime.h>
#include <cstdint>
#include <cstddef>

#define LATENT   2000
#define NG       10000
#define KER      20
#define BATCH    128
#define NTILE    80          // groups per CTA; 10000 = 125*80
#define NCTA     125
#define NTIL     125         // K16 tiles: 2000 = 125*16 exactly
#define PITCH    48          // bytes/staged row: 16 bf16 = 32B data + 16B pad
#define SROWS    208         // 128 A rows + 80 B rows
#define STG_BYTES (SROWS*PITCH)          // 9984
#define NSTG     3

#define OFF_HS   (NSTG*STG_BYTES)        // 29952 : h_s 128*80 f32
#define OFF_RS   (OFF_HS + 40960)        // 70912 : red_s 4*80
#define OFF_RQ   (OFF_RS + 1280)         // 72192 : red_q 4*80
#define OFF_SSC  (OFF_RQ + 1280)         // 73472
#define OFF_SSH  (OFF_SSC + 320)         // 73792
#define OFF_SCW  (OFF_SSH + 320)         // 74112 : conv_w 80*20
#define OFF_SCB  (OFF_SCW + 6400)        // 80512
#define SMEM_BYTES (OFF_SCB + 320)       // 80832

__device__ __forceinline__ uint32_t packbf(float lo, float hi) {
    uint32_t r;
    asm("cvt.rn.bf16x2.f32 %0, %1, %2;" : "=r"(r) : "f"(hi), "f"(lo));
    return r;
}
__device__ __forceinline__ void ldsm4(uint32_t* r, uint32_t a) {
    asm volatile("ldmatrix.sync.aligned.m8n8.x4.shared.b16 {%0,%1,%2,%3}, [%4];"
        : "=r"(r[0]), "=r"(r[1]), "=r"(r[2]), "=r"(r[3]) : "r"(a));
}
__device__ __forceinline__ void ldsm2(uint32_t* r, uint32_t a) {
    asm volatile("ldmatrix.sync.aligned.m8n8.x2.shared.b16 {%0,%1}, [%2];"
        : "=r"(r[0]), "=r"(r[1]) : "r"(a));
}
__device__ __forceinline__ void mma16816(float* d, const uint32_t* a, uint32_t b0, uint32_t b1) {
    asm volatile(
        "mma.sync.aligned.m16n8k16.row.col.f32.bf16.bf16.f32 "
        "{%0,%1,%2,%3}, {%4,%5,%6,%7}, {%8,%9}, {%0,%1,%2,%3};\n"
        : "+f"(d[0]), "+f"(d[1]), "+f"(d[2]), "+f"(d[3])
        : "r"(a[0]), "r"(a[1]), "r"(a[2]), "r"(a[3]), "r"(b0), "r"(b1));
}
__device__ __forceinline__ float sigf(float y) {
    return __fdividef(1.f, 1.f + __expf(-y));
}

__global__ void __launch_bounds__(512, 1)
fused_decoder(const float* __restrict__ z,
              const float* __restrict__ Wfc,
              const float* __restrict__ gamma,
              const float* __restrict__ beta,
              const float* __restrict__ convw,
              const float* __restrict__ convb,
              float* __restrict__ out)
{
    extern __shared__ char smem[];
    float* h_s    = (float*)(smem + OFF_HS);
    float* red_s  = (float*)(smem + OFF_RS);
    float* red_q  = (float*)(smem + OFF_RQ);
    float* sscale = (float*)(smem + OFF_SSC);
    float* sshift = (float*)(smem + OFF_SSH);
    float* scw    = (float*)(smem + OFF_SCW);
    float* scb    = (float*)(smem + OFF_SCB);

    const int tid  = threadIdx.x;
    const int w    = tid >> 5;
    const int lane = tid & 31;
    const int kq   = lane & 3;
    const int rq   = lane >> 2;
    const int g0   = blockIdx.x * NTILE;

    uint32_t smem_u32;
    asm("{ .reg .u64 t; cvta.to.shared.u64 t, %1; cvt.u32.u64 %0, t; }"
        : "=r"(smem_u32) : "l"(smem));

    // conv params (overlaps with prologue)
    for (int i = tid; i < NTILE * KER; i += 512)
        scw[i] = convw[(size_t)g0 * KER + i];
    if (tid < NTILE) scb[tid] = convb[g0 + tid];

    // ---------- MMA-warp ldmatrix offsets (warps 0..7: m32 x n40) ----------
    const int mb = (w & 3) * 32;
    const int nh = (w >> 2) * 40;
    const uint32_t aoff0 = (uint32_t)(mb + (lane & 15)) * PITCH + (lane >> 4) * 16;
    const uint32_t aoff1 = aoff0 + 16 * PITCH;
    const uint32_t brow  = 128 + nh + ((lane >> 4) << 3) + (lane & 7);
    const uint32_t bcol  = ((lane >> 3) & 1) * 16;
    const uint32_t boff0 = brow * PITCH + bcol;
    const uint32_t boff1 = boff0 + 16 * PITCH;
    const uint32_t boff2 = (uint32_t)(128 + nh + 32 + (lane & 7)) * PITCH + bcol;

    // ---------- producer setup (warps 8..15; 832 chunks of 16B f32) ----------
    const int p = (tid >= 256) ? tid - 256 : 0;
    const int nch = (p < 64) ? 4 : 3;
    const float* srcp[4];
    int stoff[4];
    #pragma unroll
    for (int j = 0; j < 4; ++j) {
        const int c = p + j * 256;
        const int cc = (c < 832) ? c : 0;
        const int row  = cc >> 2;
        const int col4 = cc & 3;
        srcp[j]  = (row < 128) ? z + (size_t)row * LATENT + col4 * 4
                               : Wfc + (size_t)(g0 + row - 128) * LATENT + col4 * 4;
        stoff[j] = row * PITCH + col4 * 8;
    }

    float4 raw[3][4];     // 3-tile f32 FIFO (worst thread: 48 regs)
    uint2  breg[4];       // 1-tile converted bf16 staging (8 regs)

    auto ldg_tile = [&](int t, int slot) {
        #pragma unroll
        for (int j = 0; j < 4; ++j) {
            if (j >= nch) break;
            raw[slot][j] = *(const float4*)(srcp[j] + t * 16);
        }
    };
    auto cvt_tile = [&](int slot) {
        #pragma unroll
        for (int j = 0; j < 4; ++j) {
            if (j >= nch) break;
            breg[j].x = packbf(raw[slot][j].x, raw[slot][j].y);
            breg[j].y = packbf(raw[slot][j].z, raw[slot][j].w);
        }
    };
    auto sts_tile = [&](int stage) {
        char* base = smem + stage * STG_BYTES;
        #pragma unroll
        for (int j = 0; j < 4; ++j) {
            if (j >= nch) break;
            *(uint2*)(base + stoff[j]) = breg[j];
        }
    };

    float d[2][5][4];
    #pragma unroll
    for (int a = 0; a < 2; ++a)
        #pragma unroll
        for (int b = 0; b < 5; ++b)
            #pragma unroll
            for (int c = 0; c < 4; ++c) d[a][b][c] = 0.f;

    // ---------- prologue ----------
    if (w >= 8) {
        ldg_tile(0, 0); ldg_tile(1, 1); ldg_tile(2, 2);
        cvt_tile(0);            // tile 0
        sts_tile(0);            // tile 0 -> stage 0
        cvt_tile(1);            // tile 1 -> breg
        ldg_tile(3, 0); ldg_tile(4, 1);
    }
    __syncthreads();

    // ---------- main loop: unroll 3, all ring indices static ----------
    #pragma unroll 1
    for (int tb = 0; tb < 42; ++tb) {
        #pragma unroll
        for (int i = 0; i < 3; ++i) {
            const int t = tb * 3 + i;
            if (t >= NTIL) break;
            if (w < 8) {
                const uint32_t base = smem_u32 + (uint32_t)(i * STG_BYTES);
                uint32_t A0[4], A1[4], B0[4], B1[4], B2[2];
                ldsm4(A0, base + aoff0);
                ldsm4(A1, base + aoff1);
                ldsm4(B0, base + boff0);
                ldsm4(B1, base + boff1);
                ldsm2(B2, base + boff2);
                mma16816(d[0][0], A0, B0[0], B0[1]);
                mma16816(d[0][1], A0, B0[2], B0[3]);
                mma16816(d[0][2], A0, B1[0], B1[1]);
                mma16816(d[0][3], A0, B1[2], B1[3]);
                mma16816(d[0][4], A0, B2[0], B2[1]);
                mma16816(d[1][0], A1, B0[0], B0[1]);
                mma16816(d[1][1], A1, B0[2], B0[3]);
                mma16816(d[1][2], A1, B1[0], B1[1]);
                mma16816(d[1][3], A1, B1[2], B1[3]);
                mma16816(d[1][4], A1, B2[0], B2[1]);
            } else {
                if (t + 1 < NTIL) sts_tile((i + 1) % 3);       // breg holds tile t+1
                if (t + 2 < NTIL) cvt_tile((i + 2) % 3);       // raw tile t+2 -> breg
                if (t + 5 < NTIL) ldg_tile(t + 5, (i + 2) % 3);
            }
            __syncthreads();
        }
    }

    // ---------- BatchNorm stats (b_fc cancels under mean subtraction) ----------
    if (w < 8) {
        #pragma unroll
        for (int nt = 0; nt < 5; ++nt) {
            float s0 = d[0][nt][0] + d[0][nt][2] + d[1][nt][0] + d[1][nt][2];
            float s1 = d[0][nt][1] + d[0][nt][3] + d[1][nt][1] + d[1][nt][3];
            float q0 = d[0][nt][0]*d[0][nt][0] + d[0][nt][2]*d[0][nt][2]
                     + d[1][nt][0]*d[1][nt][0] + d[1][nt][2]*d[1][nt][2];
            float q1 = d[0][nt][1]*d[0][nt][1] + d[0][nt][3]*d[0][nt][3]
                     + d[1][nt][1]*d[1][nt][1] + d[1][nt][3]*d[1][nt][3];
            #pragma unroll
            for (int o = 4; o < 32; o <<= 1) {
                s0 += __shfl_xor_sync(0xffffffffu, s0, o);
                s1 += __shfl_xor_sync(0xffffffffu, s1, o);
                q0 += __shfl_xor_sync(0xffffffffu, q0, o);
                q1 += __shfl_xor_sync(0xffffffffu, q1, o);
            }
            if (rq == 0) {
                const int n = nh + nt * 8 + kq * 2;
                red_s[(w & 3) * 80 + n]     = s0;
                red_s[(w & 3) * 80 + n + 1] = s1;
                red_q[(w & 3) * 80 + n]     = q0;
                red_q[(w & 3) * 80 + n + 1] = q1;
            }
        }
    }
    __syncthreads();
    if (tid < NTILE) {
        float s = 0.f, q = 0.f;
        #pragma unroll
        for (int i = 0; i < 4; ++i) { s += red_s[i * 80 + tid]; q += red_q[i * 80 + tid]; }
        const float mean = s * (1.f / BATCH);
        const float var  = q * (1.f / BATCH) - mean * mean;
        const float scv  = gamma[g0 + tid] * rsqrtf(var + 1e-5f);
        sscale[tid] = scv;
        sshift[tid] = beta[g0 + tid] - mean * scv;
    }
    __syncthreads();

    // ---------- normalize + LeakyReLU -> h_s ----------
    if (w < 8) {
        #pragma unroll
        for (int mt = 0; mt < 2; ++mt)
            #pragma unroll
            for (int nt = 0; nt < 5; ++nt)
                #pragma unroll
                for (int c = 0; c < 4; ++c) {
                    const int n = nh + nt * 8 + kq * 2 + (c & 1);
                    const int m = mb + mt * 16 + rq + ((c >> 1) << 3);
                    float hn = d[mt][nt][c] * sscale[n] + sshift[n];
                    hn = fmaxf(hn, 0.1f * hn);
                    h_s[m * 80 + n] = hn;
                }
    }
    __syncthreads();

    // ---------- epilogue: conv outer product + LeakyReLU + sigmoid, coalesced ----------
    const size_t outb = (size_t)g0 * KER;
    for (int i = tid; i < 128 * 400; i += 512) {
        const int m = i / 400;
        const int j = (i - m * 400) * 4;     // 20 % 4 == 0
        const int n = j / 20;
        const int k = j - n * 20;
        const float hn = h_s[m * 80 + n];
        const float cb = scb[n];
        const float4 wv = *(const float4*)&scw[n * KER + k];
        float4 y;
        float t0 = hn * wv.x + cb; t0 = fmaxf(t0, 0.1f * t0); y.x = sigf(t0);
        float t1 = hn * wv.y + cb; t1 = fmaxf(t1, 0.1f * t1); y.y = sigf(t1);
        float t2 = hn * wv.z + cb; t2 = fmaxf(t2, 0.1f * t2); y.z = sigf(t2);
        float t3 = hn * wv.w + cb; t3 = fmaxf(t3, 0.1f * t3); y.w = sigf(t3);
        *(float4*)(out + (size_t)m * ((size_t)NG * KER) + outb + j) = y;
    }
}

extern "C" void kernel_launch(void* const* d_in, const int* in_sizes, int n_in,
                              void* d_out, int out_size) {
    const float* z     = (const float*)d_in[0];
    const float* Wfc   = (const float*)d_in[1];
    // d_in[2] = b_fc: cancelled analytically by BN mean subtraction
    const float* gamma = (const float*)d_in[3];
    const float* beta  = (const float*)d_in[4];
    const float* convw = (const float*)d_in[5];
    const float* convb = (const float*)d_in[6];
    cudaFuncSetAttribute(fused_decoder, cudaFuncAttributeMaxDynamicSharedMemorySize, SMEM_BYTES);
    fused_decoder<<<NCTA, 512, SMEM_BYTES>>>(z, Wfc, gamma, beta, convw, convb, (float*)d_out);
}

// round 8
// speedup vs baseline: 1.6551x; 1.5296x over previous
#include <cuda_runtime.h>
#include <cstdint>
#include <cstddef>

#define LATENT   2000
#define NG       10000
#define KER      20
#define BATCH    128
#define NTILE    80            // groups per CTA; 10000 = 125*80
#define NCTA     125
#define KT       32            // K per tile
#define NTIL     63            // 2000 = 62*32 + 16 (last tile zero-padded)
#define NSTG     4
#define PF       36            // staged row pitch in floats (32 data + 4 pad): conflict-free
#define SROWS    208           // 128 A rows + 80 B rows
#define STG_BYTES (SROWS*PF*4) // 29952
#define HP       81            // h_s pitch (reduces store conflicts)

#define OFF_HS   (NSTG*STG_BYTES)        // 119808 : h_s 128*81 f32
#define OFF_RS   (OFF_HS + BATCH*HP*4)   // 161280 : red_s 4*80
#define OFF_RQ   (OFF_RS + 1280)
#define OFF_SSC  (OFF_RQ + 1280)
#define OFF_SSH  (OFF_SSC + 320)
#define OFF_SCW  (OFF_SSH + 320)         // conv_w 80*20
#define OFF_SCB  (OFF_SCW + 6400)
#define SMEM_BYTES (OFF_SCB + 320)       // 171200

__device__ __forceinline__ void cp16z(uint32_t dst, const void* src, int sz) {
    asm volatile("cp.async.cg.shared.global [%0], [%1], 16, %2;\n"
                 :: "r"(dst), "l"(src), "r"(sz));
}
__device__ __forceinline__ float sigf(float y) {
    return __fdividef(1.f, 1.f + __expf(-y));
}
__device__ __forceinline__ void mma_tf32(float* d, uint32_t a0, uint32_t a1,
                                         uint32_t a2, uint32_t a3,
                                         uint32_t b0, uint32_t b1) {
    asm volatile(
        "mma.sync.aligned.m16n8k8.row.col.f32.tf32.tf32.f32 "
        "{%0,%1,%2,%3}, {%4,%5,%6,%7}, {%8,%9}, {%0,%1,%2,%3};\n"
        : "+f"(d[0]), "+f"(d[1]), "+f"(d[2]), "+f"(d[3])
        : "r"(a0), "r"(a1), "r"(a2), "r"(a3), "r"(b0), "r"(b1));
}

__global__ void __launch_bounds__(512, 1)
fused_decoder(const float* __restrict__ z,
              const float* __restrict__ Wfc,
              const float* __restrict__ gamma,
              const float* __restrict__ beta,
              const float* __restrict__ convw,
              const float* __restrict__ convb,
              float* __restrict__ out)
{
    extern __shared__ float sm[];
    float* h_s    = (float*)((char*)sm + OFF_HS);
    float* red_s  = (float*)((char*)sm + OFF_RS);
    float* red_q  = (float*)((char*)sm + OFF_RQ);
    float* sscale = (float*)((char*)sm + OFF_SSC);
    float* sshift = (float*)((char*)sm + OFF_SSH);
    float* scw    = (float*)((char*)sm + OFF_SCW);
    float* scb    = (float*)((char*)sm + OFF_SCB);

    const int tid  = threadIdx.x;
    const int w    = tid >> 5;
    const int lane = tid & 31;
    const int kq   = lane & 3;
    const int rq   = lane >> 2;
    const int g0   = blockIdx.x * NTILE;

    uint32_t stg_u32;
    asm("{ .reg .u64 t; cvta.to.shared.u64 t, %1; cvt.u32.u64 %0, t; }"
        : "=r"(stg_u32) : "l"(sm));

    // conv params (all threads; consumed only in epilogue, many syncs later)
    for (int i = tid; i < NTILE * KER; i += 512)
        scw[i] = convw[(size_t)g0 * KER + i];
    if (tid < NTILE) scb[tid] = convb[g0 + tid];

    // ---------------- producer setup (warps 8..15; 1664 chunks of 16B) ----------------
    const int p = (tid >= 256) ? tid - 256 : 0;
    const int nch = (p < 128) ? 7 : 6;         // 128*7 + 128*6 = 1664
    const float* srcp[7];
    uint32_t dstoff[7];
    uint32_t okmask = 0;                        // chunk valid in the ragged last tile?
    #pragma unroll
    for (int j = 0; j < 7; ++j) {
        const int c = p + j * 256;
        const int cc = (c < 1664) ? c : 0;
        const int row  = cc >> 3;               // 0..207
        const int col8 = cc & 7;                // 4-float sub-column
        srcp[j]  = (row < 128) ? z + (size_t)row * LATENT + col8 * 4
                               : Wfc + (size_t)(g0 + row - 128) * LATENT + col8 * 4;
        dstoff[j] = (uint32_t)(row * PF + col8 * 4) * 4u;
        if (col8 < 4) okmask |= (1u << j);      // k = 1984 + col8*4 < 2000
    }
    auto cp_tile = [&](int t, int s) {
        const uint32_t base = stg_u32 + (uint32_t)s * STG_BYTES;
        const bool lastt = (t == NTIL - 1);
        #pragma unroll
        for (int j = 0; j < 7; ++j) {
            if (j >= nch) break;
            const int sz = (!lastt || ((okmask >> j) & 1)) ? 16 : 0;
            cp16z(base + dstoff[j], srcp[j] + (size_t)t * KT, sz);
        }
        asm volatile("cp.async.commit_group;\n");
    };

    // ---------------- consumer accumulators (warps 0..7: m32 x n40) ----------------
    const int mb = (w & 3) * 32;
    const int nh = (w >> 2) * 40;
    float d[2][5][4];
    #pragma unroll
    for (int a = 0; a < 2; ++a)
        #pragma unroll
        for (int b = 0; b < 5; ++b)
            #pragma unroll
            for (int c = 0; c < 4; ++c) d[a][b][c] = 0.f;

    auto mma_stage = [&](int s) {
        const float* zb = sm + s * (STG_BYTES / 4);
        const float* wb = zb + 128 * PF;
        #pragma unroll
        for (int ks = 0; ks < 4; ++ks) {
            const int kA = ks * 8 + kq;
            const uint32_t a00 = __float_as_uint(zb[(mb + rq)      * PF + kA]);
            const uint32_t a01 = __float_as_uint(zb[(mb + rq + 8)  * PF + kA]);
            const uint32_t a02 = __float_as_uint(zb[(mb + rq)      * PF + kA + 4]);
            const uint32_t a03 = __float_as_uint(zb[(mb + rq + 8)  * PF + kA + 4]);
            const uint32_t a10 = __float_as_uint(zb[(mb + rq + 16) * PF + kA]);
            const uint32_t a11 = __float_as_uint(zb[(mb + rq + 24) * PF + kA]);
            const uint32_t a12 = __float_as_uint(zb[(mb + rq + 16) * PF + kA + 4]);
            const uint32_t a13 = __float_as_uint(zb[(mb + rq + 24) * PF + kA + 4]);
            #pragma unroll
            for (int nt = 0; nt < 5; ++nt) {
                const uint32_t b0 = __float_as_uint(wb[(nh + nt * 8 + rq) * PF + kA]);
                const uint32_t b1 = __float_as_uint(wb[(nh + nt * 8 + rq) * PF + kA + 4]);
                mma_tf32(d[0][nt], a00, a01, a02, a03, b0, b1);
                mma_tf32(d[1][nt], a10, a11, a12, a13, b0, b1);
            }
        }
    };

    // ---------------- prologue: stages 0..2 in flight ----------------
    if (tid >= 256) {
        cp_tile(0, 0);
        cp_tile(1, 1);
        cp_tile(2, 2);
    }

    // ---------------- main loop: 63 tiles, unroll 4 (static stage ids) ----------------
    #pragma unroll 1
    for (int tb = 0; tb < 16; ++tb) {
        #pragma unroll
        for (int i = 0; i < 4; ++i) {
            const int t = tb * 4 + i;
            if (t >= NTIL) break;
            if (tid >= 256)
                asm volatile("cp.async.wait_group 2;\n");
            __syncthreads();
            if (tid >= 256) {
                if (t + 3 < NTIL) cp_tile(t + 3, (i + 3) & 3);
                else asm volatile("cp.async.commit_group;\n");
            } else {
                mma_stage(i);
            }
        }
    }
    __syncthreads();

    // ---------------- BatchNorm stats (b_fc cancels under mean subtraction) ----------------
    if (w < 8) {
        #pragma unroll
        for (int nt = 0; nt < 5; ++nt) {
            float s0 = d[0][nt][0] + d[0][nt][2] + d[1][nt][0] + d[1][nt][2];
            float s1 = d[0][nt][1] + d[0][nt][3] + d[1][nt][1] + d[1][nt][3];
            float q0 = d[0][nt][0]*d[0][nt][0] + d[0][nt][2]*d[0][nt][2]
                     + d[1][nt][0]*d[1][nt][0] + d[1][nt][2]*d[1][nt][2];
            float q1 = d[0][nt][1]*d[0][nt][1] + d[0][nt][3]*d[0][nt][3]
                     + d[1][nt][1]*d[1][nt][1] + d[1][nt][3]*d[1][nt][3];
            #pragma unroll
            for (int o = 4; o < 32; o <<= 1) {
                s0 += __shfl_xor_sync(0xffffffffu, s0, o);
                s1 += __shfl_xor_sync(0xffffffffu, s1, o);
                q0 += __shfl_xor_sync(0xffffffffu, q0, o);
                q1 += __shfl_xor_sync(0xffffffffu, q1, o);
            }
            if (rq == 0) {
                const int n = nh + nt * 8 + kq * 2;
                red_s[(w & 3) * 80 + n]     = s0;
                red_s[(w & 3) * 80 + n + 1] = s1;
                red_q[(w & 3) * 80 + n]     = q0;
                red_q[(w & 3) * 80 + n + 1] = q1;
            }
        }
    }
    __syncthreads();
    if (tid < NTILE) {
        float s = 0.f, q = 0.f;
        #pragma unroll
        for (int i = 0; i < 4; ++i) { s += red_s[i * 80 + tid]; q += red_q[i * 80 + tid]; }
        const float mean = s * (1.f / BATCH);
        const float var  = q * (1.f / BATCH) - mean * mean;
        const float scv  = gamma[g0 + tid] * rsqrtf(var + 1e-5f);
        sscale[tid] = scv;
        sshift[tid] = beta[g0 + tid] - mean * scv;
    }
    __syncthreads();

    // ---------------- normalize + LeakyReLU -> h_s ----------------
    if (w < 8) {
        #pragma unroll
        for (int mt = 0; mt < 2; ++mt)
            #pragma unroll
            for (int nt = 0; nt < 5; ++nt)
                #pragma unroll
                for (int c = 0; c < 4; ++c) {
                    const int n = nh + nt * 8 + kq * 2 + (c & 1);
                    const int m = mb + mt * 16 + rq + ((c >> 1) << 3);
                    float hn = d[mt][nt][c] * sscale[n] + sshift[n];
                    hn = fmaxf(hn, 0.1f * hn);
                    h_s[m * HP + n] = hn;
                }
    }
    __syncthreads();

    // ---------------- epilogue: conv outer product + LeakyReLU + sigmoid ----------------
    const size_t outb = (size_t)g0 * KER;
    for (int i = tid; i < 128 * 400; i += 512) {
        const int m = i / 400;
        const int j = (i - m * 400) * 4;     // 20 % 4 == 0
        const int n = j / 20;
        const int k = j - n * 20;
        const float hn = h_s[m * HP + n];
        const float cb = scb[n];
        const float4 wv = *(const float4*)&scw[n * KER + k];
        float4 y;
        float t0 = hn * wv.x + cb; t0 = fmaxf(t0, 0.1f * t0); y.x = sigf(t0);
        float t1 = hn * wv.y + cb; t1 = fmaxf(t1, 0.1f * t1); y.y = sigf(t1);
        float t2 = hn * wv.z + cb; t2 = fmaxf(t2, 0.1f * t2); y.z = sigf(t2);
        float t3 = hn * wv.w + cb; t3 = fmaxf(t3, 0.1f * t3); y.w = sigf(t3);
        *(float4*)(out + (size_t)m * ((size_t)NG * KER) + outb + j) = y;
    }
}

extern "C" void kernel_launch(void* const* d_in, const int* in_sizes, int n_in,
                              void* d_out, int out_size) {
    const float* z     = (const float*)d_in[0];
    const float* Wfc   = (const float*)d_in[1];
    // d_in[2] = b_fc: cancelled analytically by BN mean subtraction
    const float* gamma = (const float*)d_in[3];
    const float* beta  = (const float*)d_in[4];
    const float* convw = (const float*)d_in[5];
    const float* convb = (const float*)d_in[6];
    cudaFuncSetAttribute(fused_decoder, cudaFuncAttributeMaxDynamicSharedMemorySize, SMEM_BYTES);
    fused_decoder<<<NCTA, 512, SMEM_BYTES>>>(z, Wfc, gamma, beta, convw, convb, (float*)d_out);
}

// round 9
// speedup vs baseline: 1.8550x; 1.1208x over previous
#include <cuda_runtime.h>
#include <cstdint>
#include <cstddef>

#define LATENT   2000
#define NG       10000
#define KER      20
#define BATCH    128
#define NTILE    80            // groups per CTA; 10000 = 125*80
#define NCTA     125
#define KT       32            // K per tile
#define NTIL     63            // 2000 = 62*32 + 16 (last tile zero-padded)
#define NSTG     4
#define PF       36            // staged row pitch in floats (32 data + 4 pad)
#define PB       144           // pitch bytes (9*16: 16B aligned, ldsm conflict-free)
#define SROWS    208           // 128 A rows + 80 B rows
#define STG_BYTES (SROWS*PB)   // 29952
#define HP       81            // h_s pitch

#define OFF_HS   (NSTG*STG_BYTES)        // 119808 : h_s 128*81 f32
#define OFF_RS   (OFF_HS + BATCH*HP*4)   // red_s 4*80
#define OFF_RQ   (OFF_RS + 1280)
#define OFF_SSC  (OFF_RQ + 1280)
#define OFF_SSH  (OFF_SSC + 320)
#define OFF_SCW  (OFF_SSH + 320)         // conv_w 80*20
#define OFF_SCB  (OFF_SCW + 6400)
#define SMEM_BYTES (OFF_SCB + 320)       // 171200

__device__ __forceinline__ void cp16z(uint32_t dst, const void* src, int sz) {
    asm volatile("cp.async.cg.shared.global [%0], [%1], 16, %2;\n"
                 :: "r"(dst), "l"(src), "r"(sz));
}
__device__ __forceinline__ void ldsm4(uint32_t* r, uint32_t a) {
    asm volatile("ldmatrix.sync.aligned.m8n8.x4.shared.b16 {%0,%1,%2,%3}, [%4];"
        : "=r"(r[0]), "=r"(r[1]), "=r"(r[2]), "=r"(r[3]) : "r"(a));
}
__device__ __forceinline__ void ldsm2(uint32_t* r, uint32_t a) {
    asm volatile("ldmatrix.sync.aligned.m8n8.x2.shared.b16 {%0,%1}, [%2];"
        : "=r"(r[0]), "=r"(r[1]) : "r"(a));
}
__device__ __forceinline__ void mma_tf32(float* d, const uint32_t* a,
                                         uint32_t b0, uint32_t b1) {
    asm volatile(
        "mma.sync.aligned.m16n8k8.row.col.f32.tf32.tf32.f32 "
        "{%0,%1,%2,%3}, {%4,%5,%6,%7}, {%8,%9}, {%0,%1,%2,%3};\n"
        : "+f"(d[0]), "+f"(d[1]), "+f"(d[2]), "+f"(d[3])
        : "r"(a[0]), "r"(a[1]), "r"(a[2]), "r"(a[3]), "r"(b0), "r"(b1));
}
__device__ __forceinline__ float sigf(float y) {
    float t;
    asm("tanh.approx.f32 %0, %1;" : "=f"(t) : "f"(0.5f * y));
    return fmaf(0.5f, t, 0.5f);
}

__global__ void __launch_bounds__(512, 1)
fused_decoder(const float* __restrict__ z,
              const float* __restrict__ Wfc,
              const float* __restrict__ gamma,
              const float* __restrict__ beta,
              const float* __restrict__ convw,
              const float* __restrict__ convb,
              float* __restrict__ out)
{
    extern __shared__ float sm[];
    float* h_s    = (float*)((char*)sm + OFF_HS);
    float* red_s  = (float*)((char*)sm + OFF_RS);
    float* red_q  = (float*)((char*)sm + OFF_RQ);
    float* sscale = (float*)((char*)sm + OFF_SSC);
    float* sshift = (float*)((char*)sm + OFF_SSH);
    float* scw    = (float*)((char*)sm + OFF_SCW);
    float* scb    = (float*)((char*)sm + OFF_SCB);

    const int tid  = threadIdx.x;
    const int w    = tid >> 5;
    const int lane = tid & 31;
    const int kq   = lane & 3;
    const int rq   = lane >> 2;
    const int g0   = blockIdx.x * NTILE;

    uint32_t stg_u32;
    asm("{ .reg .u64 t; cvta.to.shared.u64 t, %1; cvt.u32.u64 %0, t; }"
        : "=r"(stg_u32) : "l"(sm));

    for (int i = tid; i < NTILE * KER; i += 512)
        scw[i] = convw[(size_t)g0 * KER + i];
    if (tid < NTILE) scb[tid] = convb[g0 + tid];

    // ---------------- producer setup (warps 8..15; 1664 chunks of 16B) ----------------
    const int p = (tid >= 256) ? tid - 256 : 0;
    const int nch = (p < 128) ? 7 : 6;
    const float* srcp[7];
    uint32_t dstoff[7];
    uint32_t okmask = 0;
    #pragma unroll
    for (int j = 0; j < 7; ++j) {
        const int c = p + j * 256;
        const int cc = (c < 1664) ? c : 0;
        const int row  = cc >> 3;
        const int col8 = cc & 7;
        srcp[j]  = (row < 128) ? z + (size_t)row * LATENT + col8 * 4
                               : Wfc + (size_t)(g0 + row - 128) * LATENT + col8 * 4;
        dstoff[j] = (uint32_t)(row * PB + col8 * 16);
        if (col8 < 4) okmask |= (1u << j);
    }
    auto cp_tile = [&](int t, int s) {
        const uint32_t base = stg_u32 + (uint32_t)s * STG_BYTES;
        const bool lastt = (t == NTIL - 1);
        #pragma unroll
        for (int j = 0; j < 7; ++j) {
            if (j >= nch) break;
            const int sz = (!lastt || ((okmask >> j) & 1)) ? 16 : 0;
            cp16z(base + dstoff[j], srcp[j] + (size_t)t * KT, sz);
        }
        asm volatile("cp.async.commit_group;\n");
    };

    // ---------------- consumer (warps 0..7: m32 x n40), ldmatrix offsets ----------------
    const int mb = (w & 3) * 32;
    const int nh = (w >> 2) * 40;
    // A x4 tile: lanes 0-15 -> rows mb+0..15 (regs 0,1 = m0-7,m8-15 @ k..k+3);
    //            lanes 16-31 -> same rows, k+4..k+7 (regs 2,3)
    const uint32_t aoff0 = (uint32_t)(mb + (lane & 15)) * PB + (lane >> 4) * 16;
    const uint32_t aoff1 = aoff0 + 16 * PB;
    // B x4 tile: lanes 0-7: n rows nt*8.. @k; 8-15: same n @k+4; 16-23: (nt+1)*8 @k; 24-31: @k+4
    const uint32_t boff0 = (uint32_t)(128 + nh + ((lane >> 4) << 3) + (lane & 7)) * PB
                         + ((lane >> 3) & 1) * 16;
    const uint32_t boff1 = boff0 + 16 * PB;
    // B x2 (nt=4): lanes 0-7: rows @k; 8-15: rows @k+4
    const uint32_t boff2 = (uint32_t)(128 + nh + 32 + (lane & 7)) * PB
                         + ((lane >> 3) & 1) * 16;

    float d[2][5][4];
    #pragma unroll
    for (int a = 0; a < 2; ++a)
        #pragma unroll
        for (int b = 0; b < 5; ++b)
            #pragma unroll
            for (int c = 0; c < 4; ++c) d[a][b][c] = 0.f;

    auto mma_stage = [&](int s) {
        const uint32_t base = stg_u32 + (uint32_t)s * STG_BYTES;
        #pragma unroll
        for (int ks = 0; ks < 4; ++ks) {
            const uint32_t ko = ks * 32;           // 8 floats per k-step
            uint32_t A0[4], A1[4], B01[4], B23[4], B4[2];
            ldsm4(A0,  base + aoff0 + ko);
            ldsm4(A1,  base + aoff1 + ko);
            ldsm4(B01, base + boff0 + ko);
            ldsm4(B23, base + boff1 + ko);
            ldsm2(B4,  base + boff2 + ko);
            mma_tf32(d[0][0], A0, B01[0], B01[1]);
            mma_tf32(d[0][1], A0, B01[2], B01[3]);
            mma_tf32(d[0][2], A0, B23[0], B23[1]);
            mma_tf32(d[0][3], A0, B23[2], B23[3]);
            mma_tf32(d[0][4], A0, B4[0],  B4[1]);
            mma_tf32(d[1][0], A1, B01[0], B01[1]);
            mma_tf32(d[1][1], A1, B01[2], B01[3]);
            mma_tf32(d[1][2], A1, B23[0], B23[1]);
            mma_tf32(d[1][3], A1, B23[2], B23[3]);
            mma_tf32(d[1][4], A1, B4[0],  B4[1]);
        }
    };

    // ---------------- prologue ----------------
    if (tid >= 256) {
        cp_tile(0, 0);
        cp_tile(1, 1);
        cp_tile(2, 2);
    }

    // ---------------- main loop ----------------
    #pragma unroll 1
    for (int tb = 0; tb < 16; ++tb) {
        #pragma unroll
        for (int i = 0; i < 4; ++i) {
            const int t = tb * 4 + i;
            if (t >= NTIL) break;
            if (tid >= 256)
                asm volatile("cp.async.wait_group 2;\n");
            __syncthreads();
            if (tid >= 256) {
                if (t + 3 < NTIL) cp_tile(t + 3, (i + 3) & 3);
                else asm volatile("cp.async.commit_group;\n");
            } else {
                mma_stage(i);
            }
        }
    }
    __syncthreads();

    // ---------------- BatchNorm stats (b_fc cancels under mean subtraction) ----------------
    if (w < 8) {
        #pragma unroll
        for (int nt = 0; nt < 5; ++nt) {
            float s0 = d[0][nt][0] + d[0][nt][2] + d[1][nt][0] + d[1][nt][2];
            float s1 = d[0][nt][1] + d[0][nt][3] + d[1][nt][1] + d[1][nt][3];
            float q0 = d[0][nt][0]*d[0][nt][0] + d[0][nt][2]*d[0][nt][2]
                     + d[1][nt][0]*d[1][nt][0] + d[1][nt][2]*d[1][nt][2];
            float q1 = d[0][nt][1]*d[0][nt][1] + d[0][nt][3]*d[0][nt][3]
                     + d[1][nt][1]*d[1][nt][1] + d[1][nt][3]*d[1][nt][3];
            #pragma unroll
            for (int o = 4; o < 32; o <<= 1) {
                s0 += __shfl_xor_sync(0xffffffffu, s0, o);
                s1 += __shfl_xor_sync(0xffffffffu, s1, o);
                q0 += __shfl_xor_sync(0xffffffffu, q0, o);
                q1 += __shfl_xor_sync(0xffffffffu, q1, o);
            }
            if (rq == 0) {
                const int n = nh + nt * 8 + kq * 2;
                red_s[(w & 3) * 80 + n]     = s0;
                red_s[(w & 3) * 80 + n + 1] = s1;
                red_q[(w & 3) * 80 + n]     = q0;
                red_q[(w & 3) * 80 + n + 1] = q1;
            }
        }
    }
    __syncthreads();
    if (tid < NTILE) {
        float s = 0.f, q = 0.f;
        #pragma unroll
        for (int i = 0; i < 4; ++i) { s += red_s[i * 80 + tid]; q += red_q[i * 80 + tid]; }
        const float mean = s * (1.f / BATCH);
        const float var  = q * (1.f / BATCH) - mean * mean;
        const float scv  = gamma[g0 + tid] * rsqrtf(var + 1e-5f);
        sscale[tid] = scv;
        sshift[tid] = beta[g0 + tid] - mean * scv;
    }
    __syncthreads();

    // ---------------- normalize + LeakyReLU -> h_s ----------------
    if (w < 8) {
        #pragma unroll
        for (int mt = 0; mt < 2; ++mt)
            #pragma unroll
            for (int nt = 0; nt < 5; ++nt)
                #pragma unroll
                for (int c = 0; c < 4; ++c) {
                    const int n = nh + nt * 8 + kq * 2 + (c & 1);
                    const int m = mb + mt * 16 + rq + ((c >> 1) << 3);
                    float hn = d[mt][nt][c] * sscale[n] + sshift[n];
                    hn = fmaxf(hn, 0.1f * hn);
                    h_s[m * HP + n] = hn;
                }
    }
    __syncthreads();

    // ---------------- epilogue: conv outer product + LeakyReLU + sigmoid ----------------
    const size_t outb = (size_t)g0 * KER;
    for (int i = tid; i < 128 * 400; i += 512) {
        const int m = i / 400;
        const int j = (i - m * 400) * 4;
        const int n = j / 20;
        const int k = j - n * 20;
        const float hn = h_s[m * HP + n];
        const float cb = scb[n];
        const float4 wv = *(const float4*)&scw[n * KER + k];
        float4 y;
        float t0 = hn * wv.x + cb; t0 = fmaxf(t0, 0.1f * t0); y.x = sigf(t0);
        float t1 = hn * wv.y + cb; t1 = fmaxf(t1, 0.1f * t1); y.y = sigf(t1);
        float t2 = hn * wv.z + cb; t2 = fmaxf(t2, 0.1f * t2); y.z = sigf(t2);
        float t3 = hn * wv.w + cb; t3 = fmaxf(t3, 0.1f * t3); y.w = sigf(t3);
        *(float4*)(out + (size_t)m * ((size_t)NG * KER) + outb + j) = y;
    }
}

extern "C" void kernel_launch(void* const* d_in, const int* in_sizes, int n_in,
                              void* d_out, int out_size) {
    const float* z     = (const float*)d_in[0];
    const float* Wfc   = (const float*)d_in[1];
    // d_in[2] = b_fc: cancelled analytically by BN mean subtraction
    const float* gamma = (const float*)d_in[3];
    const float* beta  = (const float*)d_in[4];
    const float* convw = (const float*)d_in[5];
    const float* convb = (const float*)d_in[6];
    cudaFuncSetAttribute(fused_decoder, cudaFuncAttributeMaxDynamicSharedMemorySize, SMEM_BYTES);
    fused_decoder<<<NCTA, 512, SMEM_BYTES>>>(z, Wfc, gamma, beta, convw, convb, (float*)d_out);
}

// round 10
// speedup vs baseline: 1.8586x; 1.0019x over previous
#include <cuda_runtime.h>
#include <cstdint>
#include <cstddef>

#define LATENT   2000
#define NG       10000
#define KER      20
#define BATCH    128
#define NTILE    80            // groups per CTA; 10000 = 125*80
#define NCTA     125
#define KT       32            // K per tile
#define NTIL     63            // 2000 = 62*32 + 16 (last tile zero-padded)
#define NSTG     4
#define PB       144           // staged row pitch bytes (9*16): ldsm conflict-free
#define SROWS    208           // 128 A rows + 80 B rows
#define STG_BYTES (SROWS*PB)   // 29952
#define HP       81            // h_s pitch

#define OFF_HS   (NSTG*STG_BYTES)        // 119808 : h_s 128*81 f32
#define OFF_RS   (OFF_HS + BATCH*HP*4)   // red_s 4*80
#define OFF_RQ   (OFF_RS + 1280)
#define OFF_SSC  (OFF_RQ + 1280)
#define OFF_SSH  (OFF_SSC + 320)
#define OFF_SCW  (OFF_SSH + 320)         // conv_w 80*20
#define OFF_SCB  (OFF_SCW + 6400)
#define OFF_BAR  (OFF_SCB + 320)         // full[4] + empty[4], 8B each
#define SMEM_BYTES (OFF_BAR + 64)

__device__ __forceinline__ void cp16z(uint32_t dst, const void* src, int sz) {
    asm volatile("cp.async.cg.shared.global [%0], [%1], 16, %2;\n"
                 :: "r"(dst), "l"(src), "r"(sz));
}
__device__ __forceinline__ void mbar_init(uint32_t mbar, uint32_t cnt) {
    asm volatile("mbarrier.init.shared.b64 [%0], %1;\n" :: "r"(mbar), "r"(cnt) : "memory");
}
__device__ __forceinline__ void mbar_arrive(uint32_t mbar) {
    asm volatile("mbarrier.arrive.shared.b64 _, [%0];\n" :: "r"(mbar) : "memory");
}
__device__ __forceinline__ void cp_arrive(uint32_t mbar) {
    asm volatile("cp.async.mbarrier.arrive.noinc.shared::cta.b64 [%0];\n"
                 :: "r"(mbar) : "memory");
}
__device__ __forceinline__ void mbar_wait(uint32_t mbar, uint32_t parity) {
    uint32_t done;
    asm volatile(
        "{\n\t.reg .pred p;\n\t"
        "mbarrier.try_wait.parity.acquire.cta.shared::cta.b64 p, [%1], %2;\n\t"
        "selp.b32 %0, 1, 0, p;\n\t}\n"
        : "=r"(done) : "r"(mbar), "r"(parity) : "memory");
    if (!done) {
        asm volatile(
            "{\n\t.reg .pred P1;\n\t"
            "W_%=:\n\t"
            "mbarrier.try_wait.parity.acquire.cta.shared::cta.b64 P1, [%0], %1, 0x989680;\n\t"
            "@P1 bra.uni D_%=;\n\t"
            "bra.uni W_%=;\n\t"
            "D_%=:\n\t}\n"
            :: "r"(mbar), "r"(parity) : "memory");
    }
}
__device__ __forceinline__ void ldsm4(uint32_t* r, uint32_t a) {
    asm volatile("ldmatrix.sync.aligned.m8n8.x4.shared.b16 {%0,%1,%2,%3}, [%4];"
        : "=r"(r[0]), "=r"(r[1]), "=r"(r[2]), "=r"(r[3]) : "r"(a));
}
__device__ __forceinline__ void ldsm2(uint32_t* r, uint32_t a) {
    asm volatile("ldmatrix.sync.aligned.m8n8.x2.shared.b16 {%0,%1}, [%2];"
        : "=r"(r[0]), "=r"(r[1]) : "r"(a));
}
__device__ __forceinline__ void mma_tf32(float* d, const uint32_t* a,
                                         uint32_t b0, uint32_t b1) {
    asm volatile(
        "mma.sync.aligned.m16n8k8.row.col.f32.tf32.tf32.f32 "
        "{%0,%1,%2,%3}, {%4,%5,%6,%7}, {%8,%9}, {%0,%1,%2,%3};\n"
        : "+f"(d[0]), "+f"(d[1]), "+f"(d[2]), "+f"(d[3])
        : "r"(a[0]), "r"(a[1]), "r"(a[2]), "r"(a[3]), "r"(b0), "r"(b1));
}
__device__ __forceinline__ float sigf(float y) {
    float t;
    asm("tanh.approx.f32 %0, %1;" : "=f"(t) : "f"(0.5f * y));
    return fmaf(0.5f, t, 0.5f);
}

__global__ void __launch_bounds__(512, 1)
fused_decoder(const float* __restrict__ z,
              const float* __restrict__ Wfc,
              const float* __restrict__ gamma,
              const float* __restrict__ beta,
              const float* __restrict__ convw,
              const float* __restrict__ convb,
              float* __restrict__ out)
{
    extern __shared__ float sm[];
    float* h_s    = (float*)((char*)sm + OFF_HS);
    float* red_s  = (float*)((char*)sm + OFF_RS);
    float* red_q  = (float*)((char*)sm + OFF_RQ);
    float* sscale = (float*)((char*)sm + OFF_SSC);
    float* sshift = (float*)((char*)sm + OFF_SSH);
    float* scw    = (float*)((char*)sm + OFF_SCW);
    float* scb    = (float*)((char*)sm + OFF_SCB);

    const int tid  = threadIdx.x;
    const int w    = tid >> 5;
    const int lane = tid & 31;
    const int kq   = lane & 3;
    const int rq   = lane >> 2;
    const int g0   = blockIdx.x * NTILE;

    uint32_t stg_u32;
    asm("{ .reg .u64 t; cvta.to.shared.u64 t, %1; cvt.u32.u64 %0, t; }"
        : "=r"(stg_u32) : "l"(sm));
    const uint32_t barF = stg_u32 + OFF_BAR;       // full[4]
    const uint32_t barE = stg_u32 + OFF_BAR + 32;  // empty[4]

    if (tid == 0) {
        #pragma unroll
        for (int s = 0; s < NSTG; ++s) {
            mbar_init(barF + s * 8, 256);   // producer threads
            mbar_init(barE + s * 8, 256);   // consumer threads
        }
    }

    for (int i = tid; i < NTILE * KER; i += 512)
        scw[i] = convw[(size_t)g0 * KER + i];
    if (tid < NTILE) scb[tid] = convb[g0 + tid];
    __syncthreads();   // mbarrier init + conv params visible

    if (tid >= 256) {
        // ================= producers (warps 8..15) =================
        const int p = tid - 256;
        const int nch = (p < 128) ? 7 : 6;       // 128*7 + 128*6 = 1664 chunks
        const float* srcp[7];
        uint32_t dstoff[7];
        uint32_t okmask = 0;
        #pragma unroll
        for (int j = 0; j < 7; ++j) {
            const int c = p + j * 256;
            const int cc = (c < 1664) ? c : 0;
            const int row  = cc >> 3;
            const int col8 = cc & 7;
            srcp[j]  = (row < 128) ? z + (size_t)row * LATENT + col8 * 4
                                   : Wfc + (size_t)(g0 + row - 128) * LATENT + col8 * 4;
            dstoff[j] = (uint32_t)(row * PB + col8 * 16);
            if (col8 < 4) okmask |= (1u << j);
        }
        int ph = 1;   // producer empty-phase starts 1: first NSTG waits pass immediately
        #pragma unroll 1
        for (int fb = 0; fb < 16; ++fb) {
            #pragma unroll
            for (int i = 0; i < 4; ++i) {
                const int f = fb * 4 + i;
                if (f >= NTIL) break;
                mbar_wait(barE + i * 8, ph);
                const uint32_t base = stg_u32 + (uint32_t)i * STG_BYTES;
                const bool lastt = (f == NTIL - 1);
                #pragma unroll
                for (int j = 0; j < 7; ++j) {
                    if (j >= nch) break;
                    const int sz = (!lastt || ((okmask >> j) & 1)) ? 16 : 0;
                    cp16z(base + dstoff[j], srcp[j] + (size_t)f * KT, sz);
                }
                cp_arrive(barF + i * 8);
            }
            ph ^= 1;
        }
    }

    // ================= consumers (warps 0..7: m32 x n40) =================
    const int mb = (w & 3) * 32;
    const int nh = (w >> 2) * 40;
    const uint32_t aoff0 = (uint32_t)(mb + (lane & 15)) * PB + (lane >> 4) * 16;
    const uint32_t aoff1 = aoff0 + 16 * PB;
    const uint32_t boff0 = (uint32_t)(128 + nh + ((lane >> 4) << 3) + (lane & 7)) * PB
                         + ((lane >> 3) & 1) * 16;
    const uint32_t boff1 = boff0 + 16 * PB;
    const uint32_t boff2 = (uint32_t)(128 + nh + 32 + (lane & 7)) * PB
                         + ((lane >> 3) & 1) * 16;

    float d[2][5][4];
    #pragma unroll
    for (int a = 0; a < 2; ++a)
        #pragma unroll
        for (int b = 0; b < 5; ++b)
            #pragma unroll
            for (int c = 0; c < 4; ++c) d[a][b][c] = 0.f;

    if (tid < 256) {
        int ph = 0;
        #pragma unroll 1
        for (int tb = 0; tb < 16; ++tb) {
            #pragma unroll
            for (int i = 0; i < 4; ++i) {
                const int t = tb * 4 + i;
                if (t >= NTIL) break;
                mbar_wait(barF + i * 8, ph);
                const uint32_t base = stg_u32 + (uint32_t)i * STG_BYTES;
                #pragma unroll
                for (int ks = 0; ks < 4; ++ks) {
                    const uint32_t ko = ks * 32;
                    uint32_t A0[4], A1[4], B01[4], B23[4], B4[2];
                    ldsm4(A0,  base + aoff0 + ko);
                    ldsm4(A1,  base + aoff1 + ko);
                    ldsm4(B01, base + boff0 + ko);
                    ldsm4(B23, base + boff1 + ko);
                    ldsm2(B4,  base + boff2 + ko);
                    mma_tf32(d[0][0], A0, B01[0], B01[1]);
                    mma_tf32(d[0][1], A0, B01[2], B01[3]);
                    mma_tf32(d[0][2], A0, B23[0], B23[1]);
                    mma_tf32(d[0][3], A0, B23[2], B23[3]);
                    mma_tf32(d[0][4], A0, B4[0],  B4[1]);
                    mma_tf32(d[1][0], A1, B01[0], B01[1]);
                    mma_tf32(d[1][1], A1, B01[2], B01[3]);
                    mma_tf32(d[1][2], A1, B23[0], B23[1]);
                    mma_tf32(d[1][3], A1, B23[2], B23[3]);
                    mma_tf32(d[1][4], A1, B4[0],  B4[1]);
                }
                mbar_arrive(barE + i * 8);
            }
            ph ^= 1;
        }
    }
    __syncthreads();

    // ================= BatchNorm stats (b_fc cancels under mean subtraction) =================
    if (w < 8) {
        #pragma unroll
        for (int nt = 0; nt < 5; ++nt) {
            float s0 = d[0][nt][0] + d[0][nt][2] + d[1][nt][0] + d[1][nt][2];
            float s1 = d[0][nt][1] + d[0][nt][3] + d[1][nt][1] + d[1][nt][3];
            float q0 = d[0][nt][0]*d[0][nt][0] + d[0][nt][2]*d[0][nt][2]
                     + d[1][nt][0]*d[1][nt][0] + d[1][nt][2]*d[1][nt][2];
            float q1 = d[0][nt][1]*d[0][nt][1] + d[0][nt][3]*d[0][nt][3]
                     + d[1][nt][1]*d[1][nt][1] + d[1][nt][3]*d[1][nt][3];
            #pragma unroll
            for (int o = 4; o < 32; o <<= 1) {
                s0 += __shfl_xor_sync(0xffffffffu, s0, o);
                s1 += __shfl_xor_sync(0xffffffffu, s1, o);
                q0 += __shfl_xor_sync(0xffffffffu, q0, o);
                q1 += __shfl_xor_sync(0xffffffffu, q1, o);
            }
            if (rq == 0) {
                const int n = nh + nt * 8 + kq * 2;
                red_s[(w & 3) * 80 + n]     = s0;
                red_s[(w & 3) * 80 + n + 1] = s1;
                red_q[(w & 3) * 80 + n]     = q0;
                red_q[(w & 3) * 80 + n + 1] = q1;
            }
        }
    }
    __syncthreads();
    if (tid < NTILE) {
        float s = 0.f, q = 0.f;
        #pragma unroll
        for (int i = 0; i < 4; ++i) { s += red_s[i * 80 + tid]; q += red_q[i * 80 + tid]; }
        const float mean = s * (1.f / BATCH);
        const float var  = q * (1.f / BATCH) - mean * mean;
        const float scv  = gamma[g0 + tid] * rsqrtf(var + 1e-5f);
        sscale[tid] = scv;
        sshift[tid] = beta[g0 + tid] - mean * scv;
    }
    __syncthreads();

    // ================= normalize + LeakyReLU -> h_s =================
    if (w < 8) {
        #pragma unroll
        for (int mt = 0; mt < 2; ++mt)
            #pragma unroll
            for (int nt = 0; nt < 5; ++nt)
                #pragma unroll
                for (int c = 0; c < 4; ++c) {
                    const int n = nh + nt * 8 + kq * 2 + (c & 1);
                    const int m = mb + mt * 16 + rq + ((c >> 1) << 3);
                    float hn = d[mt][nt][c] * sscale[n] + sshift[n];
                    hn = fmaxf(hn, 0.1f * hn);
                    h_s[m * HP + n] = hn;
                }
    }
    __syncthreads();

    // ================= epilogue: conv outer product + LeakyReLU + sigmoid =================
    const size_t outb = (size_t)g0 * KER;
    for (int i = tid; i < 128 * 400; i += 512) {
        const int m = i / 400;
        const int j = (i - m * 400) * 4;
        const int n = j / 20;
        const int k = j - n * 20;
        const float hn = h_s[m * HP + n];
        const float cb = scb[n];
        const float4 wv = *(const float4*)&scw[n * KER + k];
        float4 y;
        float t0 = hn * wv.x + cb; t0 = fmaxf(t0, 0.1f * t0); y.x = sigf(t0);
        float t1 = hn * wv.y + cb; t1 = fmaxf(t1, 0.1f * t1); y.y = sigf(t1);
        float t2 = hn * wv.z + cb; t2 = fmaxf(t2, 0.1f * t2); y.z = sigf(t2);
        float t3 = hn * wv.w + cb; t3 = fmaxf(t3, 0.1f * t3); y.w = sigf(t3);
        *(float4*)(out + (size_t)m * ((size_t)NG * KER) + outb + j) = y;
    }
}

extern "C" void kernel_launch(void* const* d_in, const int* in_sizes, int n_in,
                              void* d_out, int out_size) {
    const float* z     = (const float*)d_in[0];
    const float* Wfc   = (const float*)d_in[1];
    // d_in[2] = b_fc: cancelled analytically by BN mean subtraction
    const float* gamma = (const float*)d_in[3];
    const float* beta  = (const float*)d_in[4];
    const float* convw = (const float*)d_in[5];
    const float* convb = (const float*)d_in[6];
    cudaFuncSetAttribute(fused_decoder, cudaFuncAttributeMaxDynamicSharedMemorySize, SMEM_BYTES);
    fused_decoder<<<NCTA, 512, SMEM_BYTES>>>(z, Wfc, gamma, beta, convw, convb, (float*)d_out);
}

// round 11
// speedup vs baseline: 1.9974x; 1.0747x over previous
#include <cuda_runtime.h>
#include <cstdint>
#include <cstddef>

#define LATENT   2000
#define NG       10000
#define KER      20
#define BATCH    128
#define NTILE    80            // groups per CTA; 10000 = 125*80
#define NCTA     125
#define KT       32            // K per tile (f32 elements)
#define NTIL     63            // 2000 = 62*32 + 16 (last tile zero-padded)
#define NSTG     3             // 63 = 21*3
#define PB       80            // staged row pitch bytes (64B bf16 data + 16B pad)
#define SROWS    208           // 128 A rows + 80 B rows
#define STG_BYTES (SROWS*PB)   // 16640
#define HP       81            // h_s pitch

#define OFF_HS   (NSTG*STG_BYTES)        // 49920 : h_s 128*81 f32
#define OFF_RS   (OFF_HS + BATCH*HP*4)   // red_s 4*80
#define OFF_RQ   (OFF_RS + 1280)
#define OFF_SSC  (OFF_RQ + 1280)
#define OFF_SSH  (OFF_SSC + 320)
#define OFF_SCW  (OFF_SSH + 320)         // conv_w 80*20
#define OFF_SCB  (OFF_SCW + 6400)
#define OFF_BAR  (OFF_SCB + 320)         // full[3] + empty[3], 8B each
#define SMEM_BYTES (OFF_BAR + 48)

__device__ __forceinline__ uint32_t packbf(float lo, float hi) {
    uint32_t r;
    asm("cvt.rn.bf16x2.f32 %0, %1, %2;" : "=r"(r) : "f"(hi), "f"(lo));
    return r;
}
__device__ __forceinline__ void mbar_init(uint32_t mbar, uint32_t cnt) {
    asm volatile("mbarrier.init.shared.b64 [%0], %1;\n" :: "r"(mbar), "r"(cnt) : "memory");
}
__device__ __forceinline__ void mbar_arrive(uint32_t mbar) {
    asm volatile("mbarrier.arrive.release.cta.shared::cta.b64 _, [%0];\n"
                 :: "r"(mbar) : "memory");
}
__device__ __forceinline__ void mbar_wait(uint32_t mbar, uint32_t parity) {
    uint32_t done;
    asm volatile(
        "{\n\t.reg .pred p;\n\t"
        "mbarrier.try_wait.parity.acquire.cta.shared::cta.b64 p, [%1], %2;\n\t"
        "selp.b32 %0, 1, 0, p;\n\t}\n"
        : "=r"(done) : "r"(mbar), "r"(parity) : "memory");
    if (!done) {
        asm volatile(
            "{\n\t.reg .pred P1;\n\t"
            "W_%=:\n\t"
            "mbarrier.try_wait.parity.acquire.cta.shared::cta.b64 P1, [%0], %1, 0x989680;\n\t"
            "@P1 bra.uni D_%=;\n\t"
            "bra.uni W_%=;\n\t"
            "D_%=:\n\t}\n"
            :: "r"(mbar), "r"(parity) : "memory");
    }
}
__device__ __forceinline__ void ldsm4(uint32_t* r, uint32_t a) {
    asm volatile("ldmatrix.sync.aligned.m8n8.x4.shared.b16 {%0,%1,%2,%3}, [%4];"
        : "=r"(r[0]), "=r"(r[1]), "=r"(r[2]), "=r"(r[3]) : "r"(a));
}
__device__ __forceinline__ void ldsm2(uint32_t* r, uint32_t a) {
    asm volatile("ldmatrix.sync.aligned.m8n8.x2.shared.b16 {%0,%1}, [%2];"
        : "=r"(r[0]), "=r"(r[1]) : "r"(a));
}
__device__ __forceinline__ void mma16816(float* d, const uint32_t* a,
                                         uint32_t b0, uint32_t b1) {
    asm volatile(
        "mma.sync.aligned.m16n8k16.row.col.f32.bf16.bf16.f32 "
        "{%0,%1,%2,%3}, {%4,%5,%6,%7}, {%8,%9}, {%0,%1,%2,%3};\n"
        : "+f"(d[0]), "+f"(d[1]), "+f"(d[2]), "+f"(d[3])
        : "r"(a[0]), "r"(a[1]), "r"(a[2]), "r"(a[3]), "r"(b0), "r"(b1));
}
__device__ __forceinline__ float sigf(float y) {
    float t;
    asm("tanh.approx.f32 %0, %1;" : "=f"(t) : "f"(0.5f * y));
    return fmaf(0.5f, t, 0.5f);
}

__global__ void __launch_bounds__(512, 1)
fused_decoder(const float* __restrict__ z,
              const float* __restrict__ Wfc,
              const float* __restrict__ gamma,
              const float* __restrict__ beta,
              const float* __restrict__ convw,
              const float* __restrict__ convb,
              float* __restrict__ out)
{
    extern __shared__ float sm[];
    float* h_s    = (float*)((char*)sm + OFF_HS);
    float* red_s  = (float*)((char*)sm + OFF_RS);
    float* red_q  = (float*)((char*)sm + OFF_RQ);
    float* sscale = (float*)((char*)sm + OFF_SSC);
    float* sshift = (float*)((char*)sm + OFF_SSH);
    float* scw    = (float*)((char*)sm + OFF_SCW);
    float* scb    = (float*)((char*)sm + OFF_SCB);

    const int tid  = threadIdx.x;
    const int w    = tid >> 5;
    const int lane = tid & 31;
    const int kq   = lane & 3;
    const int rq   = lane >> 2;
    const int g0   = blockIdx.x * NTILE;

    uint32_t stg_u32;
    asm("{ .reg .u64 t; cvta.to.shared.u64 t, %1; cvt.u32.u64 %0, t; }"
        : "=r"(stg_u32) : "l"(sm));
    const uint32_t barF = stg_u32 + OFF_BAR;       // full[3]
    const uint32_t barE = stg_u32 + OFF_BAR + 24;  // empty[3]

    if (tid == 0) {
        #pragma unroll
        for (int s = 0; s < NSTG; ++s) {
            mbar_init(barF + s * 8, 256);   // producer threads
            mbar_init(barE + s * 8, 256);   // consumer threads
        }
    }
    for (int i = tid; i < NTILE * KER; i += 512)
        scw[i] = convw[(size_t)g0 * KER + i];
    if (tid < NTILE) scb[tid] = convb[g0 + tid];
    __syncthreads();   // mbarrier init + conv params visible

    if (tid >= 256) {
        // ================= producers (warps 8..15): LDG f32 -> cvt bf16 -> STS =================
        const int p = tid - 256;
        const int nch = (p < 128) ? 7 : 6;       // 128*7 + 128*6 = 1664 chunks
        const float* srcp[7];
        uint32_t dstoff[7];
        uint32_t okmask = 0;
        #pragma unroll
        for (int j = 0; j < 7; ++j) {
            const int c = p + j * 256;
            const int cc = (c < 1664) ? c : 0;
            const int row  = cc >> 3;            // 0..207
            const int col8 = cc & 7;             // 4-float sub-column
            srcp[j]  = (row < 128) ? z + (size_t)row * LATENT + col8 * 4
                                   : Wfc + (size_t)(g0 + row - 128) * LATENT + col8 * 4;
            dstoff[j] = (uint32_t)(row * PB + col8 * 8);   // 8B bf16 per chunk
            if (col8 < 4) okmask |= (1u << j);   // k = 1984 + col8*4 < 2000
        }
        float4 fifo[3][7];   // depth-3 register FIFO (producer-path-only registers)
        auto ldg_tile = [&](int t, int s) {
            #pragma unroll
            for (int j = 0; j < 7; ++j) {
                if (j >= nch) break;
                const bool v = (t < NTIL - 1) || ((okmask >> j) & 1);
                fifo[s][j] = v ? *(const float4*)(srcp[j] + (size_t)t * KT)
                               : make_float4(0.f, 0.f, 0.f, 0.f);
            }
        };
        auto sts_tile = [&](int s) {
            char* base = (char*)sm + s * STG_BYTES;
            #pragma unroll
            for (int j = 0; j < 7; ++j) {
                if (j >= nch) break;
                const float4 f = fifo[s][j];
                uint2 u;
                u.x = packbf(f.x, f.y);
                u.y = packbf(f.z, f.w);
                *(uint2*)(base + dstoff[j]) = u;
            }
        };
        ldg_tile(0, 0); ldg_tile(1, 1); ldg_tile(2, 2);
        int ph = 1;   // producer empty-phase starts 1: first NSTG waits pass immediately
        #pragma unroll 1
        for (int tb = 0; tb < 21; ++tb) {
            #pragma unroll
            for (int i = 0; i < 3; ++i) {
                const int t = tb * 3 + i;
                mbar_wait(barE + i * 8, ph);
                sts_tile(i);                      // tile t lives in fifo slot i
                mbar_arrive(barF + i * 8);        // release: STS visible to acquirers
                if (t + 3 < NTIL) ldg_tile(t + 3, i);
            }
            ph ^= 1;
        }
    }

    // ================= consumers (warps 0..7: m32 x n40, bf16 m16n8k16) =================
    const int mb = (w & 3) * 32;
    const int nh = (w >> 2) * 40;
    const uint32_t aoff0 = (uint32_t)(mb + (lane & 15)) * PB + (lane >> 4) * 16;
    const uint32_t aoff1 = aoff0 + 16 * PB;
    const uint32_t boff0 = (uint32_t)(128 + nh + ((lane >> 4) << 3) + (lane & 7)) * PB
                         + ((lane >> 3) & 1) * 16;
    const uint32_t boff1 = boff0 + 16 * PB;
    const uint32_t boff2 = (uint32_t)(128 + nh + 32 + (lane & 7)) * PB
                         + ((lane >> 3) & 1) * 16;

    float d[2][5][4];
    #pragma unroll
    for (int a = 0; a < 2; ++a)
        #pragma unroll
        for (int b = 0; b < 5; ++b)
            #pragma unroll
            for (int c = 0; c < 4; ++c) d[a][b][c] = 0.f;

    if (tid < 256) {
        int ph = 0;
        #pragma unroll 1
        for (int tb = 0; tb < 21; ++tb) {
            #pragma unroll
            for (int i = 0; i < 3; ++i) {
                mbar_wait(barF + i * 8, ph);
                const uint32_t base = stg_u32 + (uint32_t)i * STG_BYTES;
                #pragma unroll
                for (int ks = 0; ks < 2; ++ks) {
                    const uint32_t ko = ks * 32;  // 16 bf16 = 32B per k16 step
                    uint32_t A0[4], A1[4], B01[4], B23[4], B4[2];
                    ldsm4(A0,  base + aoff0 + ko);
                    ldsm4(A1,  base + aoff1 + ko);
                    ldsm4(B01, base + boff0 + ko);
                    ldsm4(B23, base + boff1 + ko);
                    ldsm2(B4,  base + boff2 + ko);
                    mma16816(d[0][0], A0, B01[0], B01[1]);
                    mma16816(d[0][1], A0, B01[2], B01[3]);
                    mma16816(d[0][2], A0, B23[0], B23[1]);
                    mma16816(d[0][3], A0, B23[2], B23[3]);
                    mma16816(d[0][4], A0, B4[0],  B4[1]);
                    mma16816(d[1][0], A1, B01[0], B01[1]);
                    mma16816(d[1][1], A1, B01[2], B01[3]);
                    mma16816(d[1][2], A1, B23[0], B23[1]);
                    mma16816(d[1][3], A1, B23[2], B23[3]);
                    mma16816(d[1][4], A1, B4[0],  B4[1]);
                }
                mbar_arrive(barE + i * 8);
            }
            ph ^= 1;
        }
    }
    __syncthreads();

    // ================= BatchNorm stats (b_fc cancels under mean subtraction) =================
    if (w < 8) {
        #pragma unroll
        for (int nt = 0; nt < 5; ++nt) {
            float s0 = d[0][nt][0] + d[0][nt][2] + d[1][nt][0] + d[1][nt][2];
            float s1 = d[0][nt][1] + d[0][nt][3] + d[1][nt][1] + d[1][nt][3];
            float q0 = d[0][nt][0]*d[0][nt][0] + d[0][nt][2]*d[0][nt][2]
                     + d[1][nt][0]*d[1][nt][0] + d[1][nt][2]*d[1][nt][2];
            float q1 = d[0][nt][1]*d[0][nt][1] + d[0][nt][3]*d[0][nt][3]
                     + d[1][nt][1]*d[1][nt][1] + d[1][nt][3]*d[1][nt][3];
            #pragma unroll
            for (int o = 4; o < 32; o <<= 1) {
                s0 += __shfl_xor_sync(0xffffffffu, s0, o);
                s1 += __shfl_xor_sync(0xffffffffu, s1, o);
                q0 += __shfl_xor_sync(0xffffffffu, q0, o);
                q1 += __shfl_xor_sync(0xffffffffu, q1, o);
            }
            if (rq == 0) {
                const int n = nh + nt * 8 + kq * 2;
                red_s[(w & 3) * 80 + n]     = s0;
                red_s[(w & 3) * 80 + n + 1] = s1;
                red_q[(w & 3) * 80 + n]     = q0;
                red_q[(w & 3) * 80 + n + 1] = q1;
            }
        }
    }
    __syncthreads();
    if (tid < NTILE) {
        float s = 0.f, q = 0.f;
        #pragma unroll
        for (int i = 0; i < 4; ++i) { s += red_s[i * 80 + tid]; q += red_q[i * 80 + tid]; }
        const float mean = s * (1.f / BATCH);
        const float var  = q * (1.f / BATCH) - mean * mean;
        const float scv  = gamma[g0 + tid] * rsqrtf(var + 1e-5f);
        sscale[tid] = scv;
        sshift[tid] = beta[g0 + tid] - mean * scv;
    }
    __syncthreads();

    // ================= normalize + LeakyReLU -> h_s =================
    if (w < 8) {
        #pragma unroll
        for (int mt = 0; mt < 2; ++mt)
            #pragma unroll
            for (int nt = 0; nt < 5; ++nt)
                #pragma unroll
                for (int c = 0; c < 4; ++c) {
                    const int n = nh + nt * 8 + kq * 2 + (c & 1);
                    const int m = mb + mt * 16 + rq + ((c >> 1) << 3);
                    float hn = d[mt][nt][c] * sscale[n] + sshift[n];
                    hn = fmaxf(hn, 0.1f * hn);
                    h_s[m * HP + n] = hn;
                }
    }
    __syncthreads();

    // ================= epilogue: conv outer product + LeakyReLU + sigmoid =================
    const size_t outb = (size_t)g0 * KER;
    for (int i = tid; i < 128 * 400; i += 512) {
        const int m = i / 400;
        const int j = (i - m * 400) * 4;
        const int n = j / 20;
        const int k = j - n * 20;
        const float hn = h_s[m * HP + n];
        const float cb = scb[n];
        const float4 wv = *(const float4*)&scw[n * KER + k];
        float4 y;
        float t0 = hn * wv.x + cb; t0 = fmaxf(t0, 0.1f * t0); y.x = sigf(t0);
        float t1 = hn * wv.y + cb; t1 = fmaxf(t1, 0.1f * t1); y.y = sigf(t1);
        float t2 = hn * wv.z + cb; t2 = fmaxf(t2, 0.1f * t2); y.z = sigf(t2);
        float t3 = hn * wv.w + cb; t3 = fmaxf(t3, 0.1f * t3); y.w = sigf(t3);
        *(float4*)(out + (size_t)m * ((size_t)NG * KER) + outb + j) = y;
    }
}

extern "C" void kernel_launch(void* const* d_in, const int* in_sizes, int n_in,
                              void* d_out, int out_size) {
    const float* z     = (const float*)d_in[0];
    const float* Wfc   = (const float*)d_in[1];
    // d_in[2] = b_fc: cancelled analytically by BN mean subtraction
    const float* gamma = (const float*)d_in[3];
    const float* beta  = (const float*)d_in[4];
    const float* convw = (const float*)d_in[5];
    const float* convb = (const float*)d_in[6];
    cudaFuncSetAttribute(fused_decoder, cudaFuncAttributeMaxDynamicSharedMemorySize, SMEM_BYTES);
    fused_decoder<<<NCTA, 512, SMEM_BYTES>>>(z, Wfc, gamma, beta, convw, convb, (float*)d_out);
}

// round 12
// speedup vs baseline: 2.2673x; 1.1352x over previous
#include <cuda_runtime.h>
#include <cstdint>
#include <cstddef>

#define LATENT   2000
#define NG       10000
#define KER      20
#define BATCH    128
#define NTILE    80            // groups per CTA; 10000 = 125*80
#define NCTA     125
#define KT       32            // K per tile (f32 elements)
#define NTIL     63            // 2000 = 62*32 + 16 (last tile zero-padded)
#define NSTG     3             // 63 = 21*3
#define PB       80            // staged row pitch bytes (64B bf16 data + 16B pad)
#define SROWS    208           // 128 A rows + 80 B rows
#define STG_BYTES (SROWS*PB)   // 16640
#define HP       81            // h_s pitch

#define OFF_HS   (NSTG*STG_BYTES)        // 49920 : h_s 128*81 f32
#define OFF_RS   (OFF_HS + BATCH*HP*4)   // 91392 : red_s 2*80
#define OFF_RQ   (OFF_RS + 640)          // red_q 2*80
#define OFF_SSC  (OFF_RQ + 640)
#define OFF_SSH  (OFF_SSC + 320)
#define OFF_SCW  (OFF_SSH + 320)         // conv_w 80*20
#define OFF_SCB  (OFF_SCW + 6400)
#define OFF_BAR  (OFF_SCB + 320)         // full[3] + empty[3], 8B each
#define SMEM_BYTES (OFF_BAR + 48)

__device__ __forceinline__ uint32_t packbf(float lo, float hi) {
    uint32_t r;
    asm("cvt.rn.bf16x2.f32 %0, %1, %2;" : "=r"(r) : "f"(hi), "f"(lo));
    return r;
}
__device__ __forceinline__ void mbar_init(uint32_t mbar, uint32_t cnt) {
    asm volatile("mbarrier.init.shared.b64 [%0], %1;\n" :: "r"(mbar), "r"(cnt) : "memory");
}
__device__ __forceinline__ void mbar_arrive(uint32_t mbar) {
    asm volatile("mbarrier.arrive.release.cta.shared::cta.b64 _, [%0];\n"
                 :: "r"(mbar) : "memory");
}
__device__ __forceinline__ void mbar_wait(uint32_t mbar, uint32_t parity) {
    uint32_t done;
    asm volatile(
        "{\n\t.reg .pred p;\n\t"
        "mbarrier.try_wait.parity.acquire.cta.shared::cta.b64 p, [%1], %2;\n\t"
        "selp.b32 %0, 1, 0, p;\n\t}\n"
        : "=r"(done) : "r"(mbar), "r"(parity) : "memory");
    if (!done) {
        asm volatile(
            "{\n\t.reg .pred P1;\n\t"
            "W_%=:\n\t"
            "mbarrier.try_wait.parity.acquire.cta.shared::cta.b64 P1, [%0], %1, 0x989680;\n\t"
            "@P1 bra.uni D_%=;\n\t"
            "bra.uni W_%=;\n\t"
            "D_%=:\n\t}\n"
            :: "r"(mbar), "r"(parity) : "memory");
    }
}
__device__ __forceinline__ void ldsm4(uint32_t* r, uint32_t a) {
    asm volatile("ldmatrix.sync.aligned.m8n8.x4.shared.b16 {%0,%1,%2,%3}, [%4];"
        : "=r"(r[0]), "=r"(r[1]), "=r"(r[2]), "=r"(r[3]) : "r"(a));
}
__device__ __forceinline__ void ldsm2(uint32_t* r, uint32_t a) {
    asm volatile("ldmatrix.sync.aligned.m8n8.x2.shared.b16 {%0,%1}, [%2];"
        : "=r"(r[0]), "=r"(r[1]) : "r"(a));
}
__device__ __forceinline__ void mma16816(float* d, const uint32_t* a,
                                         uint32_t b0, uint32_t b1) {
    asm volatile(
        "mma.sync.aligned.m16n8k16.row.col.f32.bf16.bf16.f32 "
        "{%0,%1,%2,%3}, {%4,%5,%6,%7}, {%8,%9}, {%0,%1,%2,%3};\n"
        : "+f"(d[0]), "+f"(d[1]), "+f"(d[2]), "+f"(d[3])
        : "r"(a[0]), "r"(a[1]), "r"(a[2]), "r"(a[3]), "r"(b0), "r"(b1));
}
__device__ __forceinline__ float sigf(float y) {
    float t;
    asm("tanh.approx.f32 %0, %1;" : "=f"(t) : "f"(0.5f * y));
    return fmaf(0.5f, t, 0.5f);
}

__global__ void __launch_bounds__(512, 1)
fused_decoder(const float* __restrict__ z,
              const float* __restrict__ Wfc,
              const float* __restrict__ gamma,
              const float* __restrict__ beta,
              const float* __restrict__ convw,
              const float* __restrict__ convb,
              float* __restrict__ out)
{
    extern __shared__ float sm[];
    float* h_s    = (float*)((char*)sm + OFF_HS);
    float* red_s  = (float*)((char*)sm + OFF_RS);
    float* red_q  = (float*)((char*)sm + OFF_RQ);
    float* sscale = (float*)((char*)sm + OFF_SSC);
    float* sshift = (float*)((char*)sm + OFF_SSH);
    float* scw    = (float*)((char*)sm + OFF_SCW);
    float* scb    = (float*)((char*)sm + OFF_SCB);

    const int tid  = threadIdx.x;
    const int w    = tid >> 5;
    const int lane = tid & 31;
    const int kq   = lane & 3;
    const int rq   = lane >> 2;
    const int g0   = blockIdx.x * NTILE;

    uint32_t stg_u32;
    asm("{ .reg .u64 t; cvta.to.shared.u64 t, %1; cvt.u32.u64 %0, t; }"
        : "=r"(stg_u32) : "l"(sm));
    const uint32_t barF = stg_u32 + OFF_BAR;       // full[3]
    const uint32_t barE = stg_u32 + OFF_BAR + 24;  // empty[3]

    if (tid == 0) {
        #pragma unroll
        for (int s = 0; s < NSTG; ++s) {
            mbar_init(barF + s * 8, 384);   // producer threads (12 warps)
            mbar_init(barE + s * 8, 128);   // consumer threads (4 warps)
        }
    }
    for (int i = tid; i < NTILE * KER; i += 512)
        scw[i] = convw[(size_t)g0 * KER + i];
    if (tid < NTILE) scb[tid] = convb[g0 + tid];
    __syncthreads();   // mbarrier init + conv params visible

    if (tid >= 128) {
        // ======== producers (warps 4..15, 384 threads): LDG f32 -> cvt bf16 -> STS ========
        const int p = tid - 128;
        const int nch = (p < 128) ? 5 : 4;       // 128*5 + 256*4 = 1664 chunks
        const float* srcp[5];
        uint32_t dstoff[5];
        uint32_t okmask = 0;
        #pragma unroll
        for (int j = 0; j < 5; ++j) {
            const int c = p + j * 384;
            const int cc = (c < 1664) ? c : 0;
            const int row  = cc >> 3;            // 0..207
            const int col8 = cc & 7;             // 4-float sub-column
            srcp[j]  = (row < 128) ? z + (size_t)row * LATENT + col8 * 4
                                   : Wfc + (size_t)(g0 + row - 128) * LATENT + col8 * 4;
            dstoff[j] = (uint32_t)(row * PB + col8 * 8);   // 8B bf16 per chunk
            if (col8 < 4) okmask |= (1u << j);   // k = 1984 + col8*4 < 2000
        }
        float4 fifo[3][5];   // depth-3 register FIFO (producer-path-only registers)
        auto ldg_tile = [&](int t, int s) {
            #pragma unroll
            for (int j = 0; j < 5; ++j) {
                if (j >= nch) break;
                const bool v = (t < NTIL - 1) || ((okmask >> j) & 1);
                fifo[s][j] = v ? *(const float4*)(srcp[j] + (size_t)t * KT)
                               : make_float4(0.f, 0.f, 0.f, 0.f);
            }
        };
        auto sts_tile = [&](int s) {
            char* base = (char*)sm + s * STG_BYTES;
            #pragma unroll
            for (int j = 0; j < 5; ++j) {
                if (j >= nch) break;
                const float4 f = fifo[s][j];
                uint2 u;
                u.x = packbf(f.x, f.y);
                u.y = packbf(f.z, f.w);
                *(uint2*)(base + dstoff[j]) = u;
            }
        };
        ldg_tile(0, 0); ldg_tile(1, 1); ldg_tile(2, 2);
        int ph = 1;   // producer empty-phase starts 1: first NSTG waits pass immediately
        #pragma unroll 1
        for (int tb = 0; tb < 21; ++tb) {
            #pragma unroll
            for (int i = 0; i < 3; ++i) {
                const int t = tb * 3 + i;
                mbar_wait(barE + i * 8, ph);
                sts_tile(i);                      // tile t lives in fifo slot i
                mbar_arrive(barF + i * 8);        // release: STS visible to acquirers
                if (t + 3 < NTIL) ldg_tile(t + 3, i);
            }
            ph ^= 1;
        }
    }

    // ======== consumers (warps 0..3: m64 x n40 each, bf16 m16n8k16) ========
    const int mb = (w & 1) * 64;          // 2 m-blocks of 64
    const int nh = (w >> 1) * 40;         // 2 n-halves of 40
    const uint32_t aoffb = (uint32_t)(mb + (lane & 15)) * PB + (lane >> 4) * 16;
    const uint32_t boff0 = (uint32_t)(128 + nh + ((lane >> 4) << 3) + (lane & 7)) * PB
                         + ((lane >> 3) & 1) * 16;
    const uint32_t boff1 = boff0 + 16 * PB;
    const uint32_t boff2 = (uint32_t)(128 + nh + 32 + (lane & 7)) * PB
                         + ((lane >> 3) & 1) * 16;

    float d[4][5][4];
    #pragma unroll
    for (int a = 0; a < 4; ++a)
        #pragma unroll
        for (int b = 0; b < 5; ++b)
            #pragma unroll
            for (int c = 0; c < 4; ++c) d[a][b][c] = 0.f;

    if (tid < 128) {
        int ph = 0;
        #pragma unroll 1
        for (int tb = 0; tb < 21; ++tb) {
            #pragma unroll
            for (int i = 0; i < 3; ++i) {
                mbar_wait(barF + i * 8, ph);
                const uint32_t base = stg_u32 + (uint32_t)i * STG_BYTES;
                #pragma unroll
                for (int ks = 0; ks < 2; ++ks) {
                    const uint32_t ko = ks * 32;  // 16 bf16 = 32B per k16 step
                    uint32_t B01[4], B23[4], B4[2];
                    ldsm4(B01, base + boff0 + ko);
                    ldsm4(B23, base + boff1 + ko);
                    ldsm2(B4,  base + boff2 + ko);
                    #pragma unroll
                    for (int mt = 0; mt < 4; ++mt) {
                        uint32_t A[4];
                        ldsm4(A, base + aoffb + (uint32_t)(mt * 16 * PB) + ko);
                        if (ks == 1 && mt == 3)
                            mbar_arrive(barE + i * 8);   // all stage reads issued
                        mma16816(d[mt][0], A, B01[0], B01[1]);
                        mma16816(d[mt][1], A, B01[2], B01[3]);
                        mma16816(d[mt][2], A, B23[0], B23[1]);
                        mma16816(d[mt][3], A, B23[2], B23[3]);
                        mma16816(d[mt][4], A, B4[0],  B4[1]);
                    }
                }
            }
            ph ^= 1;
        }
    }
    __syncthreads();

    // ======== BatchNorm stats (b_fc cancels under mean subtraction) ========
    if (w < 4) {
        #pragma unroll
        for (int nt = 0; nt < 5; ++nt) {
            float s0 = 0.f, s1 = 0.f, q0 = 0.f, q1 = 0.f;
            #pragma unroll
            for (int mt = 0; mt < 4; ++mt) {
                s0 += d[mt][nt][0] + d[mt][nt][2];
                s1 += d[mt][nt][1] + d[mt][nt][3];
                q0 += d[mt][nt][0]*d[mt][nt][0] + d[mt][nt][2]*d[mt][nt][2];
                q1 += d[mt][nt][1]*d[mt][nt][1] + d[mt][nt][3]*d[mt][nt][3];
            }
            #pragma unroll
            for (int o = 4; o < 32; o <<= 1) {
                s0 += __shfl_xor_sync(0xffffffffu, s0, o);
                s1 += __shfl_xor_sync(0xffffffffu, s1, o);
                q0 += __shfl_xor_sync(0xffffffffu, q0, o);
                q1 += __shfl_xor_sync(0xffffffffu, q1, o);
            }
            if (rq == 0) {
                const int n = nh + nt * 8 + kq * 2;
                red_s[(w & 1) * 80 + n]     = s0;
                red_s[(w & 1) * 80 + n + 1] = s1;
                red_q[(w & 1) * 80 + n]     = q0;
                red_q[(w & 1) * 80 + n + 1] = q1;
            }
        }
    }
    __syncthreads();
    if (tid < NTILE) {
        const float s = red_s[tid] + red_s[80 + tid];
        const float q = red_q[tid] + red_q[80 + tid];
        const float mean = s * (1.f / BATCH);
        const float var  = q * (1.f / BATCH) - mean * mean;
        const float scv  = gamma[g0 + tid] * rsqrtf(var + 1e-5f);
        sscale[tid] = scv;
        sshift[tid] = beta[g0 + tid] - mean * scv;
    }
    __syncthreads();

    // ======== normalize + LeakyReLU -> h_s ========
    if (w < 4) {
        #pragma unroll
        for (int mt = 0; mt < 4; ++mt)
            #pragma unroll
            for (int nt = 0; nt < 5; ++nt)
                #pragma unroll
                for (int c = 0; c < 4; ++c) {
                    const int n = nh + nt * 8 + kq * 2 + (c & 1);
                    const int m = mb + mt * 16 + rq + ((c >> 1) << 3);
                    float hn = d[mt][nt][c] * sscale[n] + sshift[n];
                    hn = fmaxf(hn, 0.1f * hn);
                    h_s[m * HP + n] = hn;
                }
    }
    __syncthreads();

    // ======== epilogue: conv outer product + LeakyReLU + sigmoid ========
    const size_t outb = (size_t)g0 * KER;
    for (int i = tid; i < 128 * 400; i += 512) {
        const int m = i / 400;
        const int j = (i - m * 400) * 4;
        const int n = j / 20;
        const int k = j - n * 20;
        const float hn = h_s[m * HP + n];
        const float cb = scb[n];
        const float4 wv = *(const float4*)&scw[n * KER + k];
        float4 y;
        float t0 = hn * wv.x + cb; t0 = fmaxf(t0, 0.1f * t0); y.x = sigf(t0);
        float t1 = hn * wv.y + cb; t1 = fmaxf(t1, 0.1f * t1); y.y = sigf(t1);
        float t2 = hn * wv.z + cb; t2 = fmaxf(t2, 0.1f * t2); y.z = sigf(t2);
        float t3 = hn * wv.w + cb; t3 = fmaxf(t3, 0.1f * t3); y.w = sigf(t3);
        *(float4*)(out + (size_t)m * ((size_t)NG * KER) + outb + j) = y;
    }
}

extern "C" void kernel_launch(void* const* d_in, const int* in_sizes, int n_in,
                              void* d_out, int out_size) {
    const float* z     = (const float*)d_in[0];
    const float* Wfc   = (const float*)d_in[1];
    // d_in[2] = b_fc: cancelled analytically by BN mean subtraction
    const float* gamma = (const float*)d_in[3];
    const float* beta  = (const float*)d_in[4];
    const float* convw = (const float*)d_in[5];
    const float* convb = (const float*)d_in[6];
    cudaFuncSetAttribute(fused_decoder, cudaFuncAttributeMaxDynamicSharedMemorySize, SMEM_BYTES);
    fused_decoder<<<NCTA, 512, SMEM_BYTES>>>(z, Wfc, gamma, beta, convw, convb, (float*)d_out);
}